// round 1
// baseline (speedup 1.0000x reference)
#include <cuda_runtime.h>
#include <cstdint>

#define BATCH 4
#define CHAN  128
#define CF    64
#define HW    9216
#define MH    2304
#define NEGF  (-3.402823466e38f)

__device__ float g_rn_f [BATCH * HW];
__device__ float g_rn_l [BATCH * HW];
__device__ float g_rn_fl[BATCH * HW];
__device__ float g_max[2][BATCH * MH];
__device__ int   g_arg[2][BATCH * MH];
__device__ int   g_colflag[2][BATCH * HW];
__device__ unsigned char g_selmap[BATCH * HW];
__device__ float g_S[BATCH][2][CF];

__global__ void norms_kernel(const float* __restrict__ x,
                             const float* __restrict__ flip)
{
    int j = blockIdx.x * 256 + threadIdx.x;
    int b = blockIdx.y;
    if (j >= HW) return;
    const float* fx = x + (size_t)b * CHAN * HW;
    const float* lx = fx + (size_t)CF * HW;
    const float* fp = flip + (size_t)b * CF * HW;
    float nf = 0.f, nl = 0.f, nfl = 0.f;
#pragma unroll 8
    for (int c = 0; c < CF; c++) {
        float a = fx[(size_t)c * HW + j];  nf  += a * a;
        float l = lx[(size_t)c * HW + j];  nl  += l * l;
        float d = fp[(size_t)c * HW + j];  nfl += d * d;
    }
    g_rn_f [b * HW + j] = 1.0f / sqrtf(nf);
    g_rn_l [b * HW + j] = 1.0f / sqrtf(nl);
    g_rn_fl[b * HW + j] = 1.0f / sqrtf(nfl);
}

__global__ void __launch_bounds__(256)
score_kernel(const float* __restrict__ x, const float* __restrict__ flip,
             const int* __restrict__ flag, const int* __restrict__ flagf,
             const int* __restrict__ p,   const int* __restrict__ q)
{
    __shared__ __align__(16) float As[64 * 64];
    __shared__ __align__(16) float Bs[64 * 64];
    __shared__ int rowPix[64];

    const int rowBlk = blockIdx.x;
    const int b      = blockIdx.y;
    const int br     = blockIdx.z;
    const int tid = threadIdx.x;
    const int tx = tid & 15, ty = tid >> 4;

    const int*   idx   = (br ? q : p) + b * MH;
    const float* Amat  = x + (size_t)b * CHAN * HW;
    const float* Bmat  = br ? (flip + (size_t)b * CF * HW)
                            : (x + (size_t)b * CHAN * HW + (size_t)CF * HW);
    const int*   fl    = (br ? flagf : flag) + b * HW;
    const float* rncol = (br ? g_rn_fl : g_rn_l) + b * HW;

    if (tid < 64) rowPix[tid] = idx[rowBlk * 64 + tid];
    __syncthreads();

    for (int t = tid; t < 64 * 64; t += 256) {
        int r = t & 63, k = t >> 6;
        As[k * 64 + r] = Amat[(size_t)k * HW + rowPix[r]];
    }

    float rnr[4];
#pragma unroll
    for (int i = 0; i < 4; i++)
        rnr[i] = g_rn_f[b * HW + rowPix[ty * 4 + i]];

    float best[4];  int bestj[4];
#pragma unroll
    for (int i = 0; i < 4; i++) { best[i] = __int_as_float(0xff800000); bestj[i] = 0; }

    for (int jt = 0; jt < HW; jt += 64) {
        __syncthreads();
        for (int t = tid; t < 1024; t += 256) {
            int k  = t >> 4;
            int c4 = (t & 15) * 4;
            float4 v = *reinterpret_cast<const float4*>(&Bmat[(size_t)k * HW + jt + c4]);
            *reinterpret_cast<float4*>(&Bs[k * 64 + c4]) = v;
        }
        __syncthreads();

        float acc[4][4] = {{0.f}};
#pragma unroll 8
        for (int k = 0; k < 64; k++) {
            float4 av = *reinterpret_cast<const float4*>(&As[k * 64 + (ty << 2)]);
            float4 bv = *reinterpret_cast<const float4*>(&Bs[k * 64 + (tx << 2)]);
            float ar[4]  = {av.x, av.y, av.z, av.w};
            float brr[4] = {bv.x, bv.y, bv.z, bv.w};
#pragma unroll
            for (int i = 0; i < 4; i++)
#pragma unroll
                for (int jj = 0; jj < 4; jj++)
                    acc[i][jj] += ar[i] * brr[jj];
        }

#pragma unroll
        for (int jj = 0; jj < 4; jj++) {
            int col = jt + (tx << 2) + jj;
            int msk = fl[col];
            float sc = rncol[col];
#pragma unroll
            for (int i = 0; i < 4; i++) {
                float v = msk ? NEGF : acc[i][jj] * sc * rnr[i];
                if (v > best[i]) { best[i] = v; bestj[i] = col; }
            }
        }
    }

    __syncthreads();
    float* rv = Bs;
    int*   rj = reinterpret_cast<int*>(As);
#pragma unroll
    for (int i = 0; i < 4; i++) {
        rv[(ty * 4 + i) * 16 + tx] = best[i];
        rj[(ty * 4 + i) * 16 + tx] = bestj[i];
    }
    __syncthreads();
    if (tid < 64) {
        float bv = __int_as_float(0xff800000);
        int bj = 0x7fffffff;
        for (int t = 0; t < 16; t++) {
            float v  = rv[tid * 16 + t];
            int   j2 = rj[tid * 16 + t];
            if (v > bv || (v == bv && j2 < bj)) { bv = v; bj = j2; }
        }
        int gi = b * MH + rowBlk * 64 + tid;
        g_max[br][gi] = bv;
        g_arg[br][gi] = bj;
    }
}

__global__ void zero_kernel()
{
    int t = blockIdx.x * 256 + threadIdx.x;
    if (t < 2 * BATCH * HW) (&g_colflag[0][0])[t] = 0;
    if (t < BATCH * HW) g_selmap[t] = 0;
}

__global__ void scatter_kernel(const int* __restrict__ p)
{
    int t = blockIdx.x * 256 + threadIdx.x;
    if (t >= BATCH * MH) return;
    int b = t / MH;
    g_colflag[0][b * HW + g_arg[0][t]] = 1;
    g_colflag[1][b * HW + g_arg[1][t]] = 1;
    int pix = p[t];
    if (pix != 0)
        g_selmap[b * HW + pix] = (g_max[0][t] >= g_max[1][t]) ? 1 : 2;
}

__global__ void ssum_kernel(const float* __restrict__ x, const float* __restrict__ flip)
{
    int c  = blockIdx.x;
    int b  = blockIdx.y;
    int br = blockIdx.z;
    const float* Bmat = br ? (flip + (size_t)b * CF * HW)
                           : (x + (size_t)b * CHAN * HW + (size_t)CF * HW);
    const int* cfl = g_colflag[br] + b * HW;
    float s = 0.f;
    for (int j = threadIdx.x; j < HW; j += 256)
        if (cfl[j]) s += Bmat[(size_t)c * HW + j];
    __shared__ float red[256];
    red[threadIdx.x] = s;
    __syncthreads();
    for (int off = 128; off > 0; off >>= 1) {
        if (threadIdx.x < off) red[threadIdx.x] += red[threadIdx.x + off];
        __syncthreads();
    }
    if (threadIdx.x == 0) g_S[b][br][c] = red[0];
}

__global__ void out_kernel(const float* __restrict__ x, float* __restrict__ out)
{
    unsigned int idx = blockIdx.x * 256u + threadIdx.x;
    const unsigned int total = BATCH * 192u * HW;
    if (idx >= total) return;
    unsigned int b   = idx / (192u * HW);
    unsigned int rem = idx - b * 192u * HW;
    unsigned int ch  = rem / HW;
    unsigned int j   = rem - ch * HW;
    float v;
    if (ch < CHAN) {
        v = x[(size_t)b * CHAN * HW + rem];
    } else {
        int s = g_selmap[b * HW + j];
        v = s ? g_S[b][s - 1][ch - CHAN] : 0.f;
    }
    out[idx] = v;
}

extern "C" void kernel_launch(void* const* d_in, const int* in_sizes, int n_in,
                              void* d_out, int out_size)
{
    const float* x     = (const float*)d_in[0];
    const float* flip  = (const float*)d_in[1];
    const int*   flag  = (const int*)d_in[2];
    const int*   flagf = (const int*)d_in[3];
    const int*   p     = (const int*)d_in[4];
    const int*   q     = (const int*)d_in[5];
    float* out = (float*)d_out;

    norms_kernel  <<<dim3(HW / 256, BATCH), 256>>>(x, flip);
    score_kernel  <<<dim3(MH / 64, BATCH, 2), 256>>>(x, flip, flag, flagf, p, q);
    zero_kernel   <<<(2 * BATCH * HW + 255) / 256, 256>>>();
    scatter_kernel<<<(BATCH * MH + 255) / 256, 256>>>(p);
    ssum_kernel   <<<dim3(CF, BATCH, 2), 256>>>(x, flip);
    out_kernel    <<<(BATCH * 192 * HW + 255) / 256, 256>>>(x, out);
}

// round 2
// speedup vs baseline: 1.3311x; 1.3311x over previous
#include <cuda_runtime.h>
#include <cstdint>

#define BATCH 4
#define CHAN  128
#define CF    64
#define HW    9216
#define MH    2304
#define NC    (HW - MH)        // 6912 unmasked columns per branch (108 tiles of 64)

// ---------------- scratch (__device__ globals; no allocations allowed) -----
__device__ float g_rn_f [BATCH * HW];
__device__ float g_rn_l [BATCH * HW];
__device__ float g_rn_fl[BATCH * HW];
__device__ int   g_colidx[2][BATCH][NC];   // compacted -> original column index
__device__ float g_rnc   [2][BATCH][NC];   // compacted column inverse norms
__device__ float g_Bc    [2][BATCH][CF][NC]; // compacted B matrices (14.2 MB)
__device__ float g_max[2][BATCH * MH];
__device__ int   g_arg[2][BATCH * MH];
__device__ int   g_colflag[2][BATCH * HW];
__device__ unsigned char g_selmap[BATCH * HW];
__device__ float g_S[BATCH][2][CF];

// ---------------- packed f32x2 helpers -------------------------------------
__device__ __forceinline__ void ffma2(unsigned long long& acc,
                                      unsigned long long a,
                                      unsigned long long b)
{
    asm("fma.rn.f32x2 %0, %1, %2, %0;" : "+l"(acc) : "l"(a), "l"(b));
}
__device__ __forceinline__ unsigned long long dup2(float a)
{
    unsigned long long r;
    asm("mov.b64 %0, {%1, %1};" : "=l"(r) : "r"(__float_as_uint(a)));
    return r;
}

// ---------------- kernel A: per-pixel inverse norms ------------------------
__global__ void norms_kernel(const float* __restrict__ x,
                             const float* __restrict__ flip)
{
    int j = blockIdx.x * 256 + threadIdx.x;
    int b = blockIdx.y;
    if (j >= HW) return;
    const float* fx = x + (size_t)b * CHAN * HW;
    const float* lx = fx + (size_t)CF * HW;
    const float* fp = flip + (size_t)b * CF * HW;
    float nf = 0.f, nl = 0.f, nfl = 0.f;
#pragma unroll 8
    for (int c = 0; c < CF; c++) {
        float a = fx[(size_t)c * HW + j];  nf  += a * a;
        float l = lx[(size_t)c * HW + j];  nl  += l * l;
        float d = fp[(size_t)c * HW + j];  nfl += d * d;
    }
    g_rn_f [b * HW + j] = 1.0f / sqrtf(nf);
    g_rn_l [b * HW + j] = 1.0f / sqrtf(nl);
    g_rn_fl[b * HW + j] = 1.0f / sqrtf(nfl);
}

// ---------------- kernel A2: order-preserving column compaction ------------
// grid (BATCH, 2), block 1024; each thread scans HW/1024 = 9 elems
__global__ void compact_kernel(const int* __restrict__ flag,
                               const int* __restrict__ flagf)
{
    const int b = blockIdx.x, br = blockIdx.y;
    const int*   fl = (br ? flagf : flag) + b * HW;
    const float* rn = (br ? g_rn_fl : g_rn_l) + b * HW;
    __shared__ int cnt[1024];
    const int t = threadIdx.x;
    const int PER = HW / 1024;             // 9
    const int base = t * PER;
    int c = 0;
#pragma unroll
    for (int i = 0; i < PER; i++) c += (fl[base + i] == 0);
    cnt[t] = c;
    __syncthreads();
    for (int off = 1; off < 1024; off <<= 1) {
        int v = (t >= off) ? cnt[t - off] : 0;
        __syncthreads();
        cnt[t] += v;
        __syncthreads();
    }
    int pos = cnt[t] - c;                  // exclusive prefix
#pragma unroll
    for (int i = 0; i < PER; i++) {
        int j = base + i;
        if (fl[j] == 0) {
            g_colidx[br][b][pos] = j;
            g_rnc   [br][b][pos] = rn[j];
            pos++;
        }
    }
}

// ---------------- kernel A3: gather compacted B ----------------------------
// grid (NC/256, CF, BATCH*2), block 256
__global__ void bgather_kernel(const float* __restrict__ x,
                               const float* __restrict__ flip)
{
    int cc = blockIdx.x * 256 + threadIdx.x;
    int k  = blockIdx.y;
    int bb = blockIdx.z;
    int b = bb >> 1, br = bb & 1;
    const float* Bmat = br ? (flip + (size_t)b * CF * HW)
                           : (x + (size_t)b * CHAN * HW + (size_t)CF * HW);
    g_Bc[br][b][k][cc] = Bmat[(size_t)k * HW + g_colidx[br][b][cc]];
}

// ---------------- kernel B: scored argmax GEMM (f32x2, compacted cols) -----
// grid: (MH/64, BATCH, 2), block 256 (16x16 threads, 4x4 micro-tile)
__global__ void __launch_bounds__(256)
score_kernel(const float* __restrict__ x,
             const int* __restrict__ p, const int* __restrict__ q)
{
    __shared__ __align__(16) float As[64 * 64];   // As[k*64 + r]
    __shared__ __align__(16) float Bs[64 * 64];   // Bs[k*64 + c]
    __shared__ int rowPix[64];

    const int rowBlk = blockIdx.x;
    const int b      = blockIdx.y;
    const int br     = blockIdx.z;
    const int tid = threadIdx.x;
    const int tx = tid & 15, ty = tid >> 4;

    const int*   idx   = (br ? q : p) + b * MH;
    const float* Amat  = x + (size_t)b * CHAN * HW;      // former half
    const float* Bmat  = &g_Bc[br][b][0][0];             // [CF][NC] compacted
    const int*   cidx  = g_colidx[br][b];
    const float* rnc   = g_rnc[br][b];

    if (tid < 64) rowPix[tid] = idx[rowBlk * 64 + tid];
    __syncthreads();

    // A tile: As[k][r] = former[k][rowPix[r]]
    for (int t = tid; t < 64 * 64; t += 256) {
        int r = t & 63, k = t >> 6;
        As[k * 64 + r] = Amat[(size_t)k * HW + rowPix[r]];
    }

    float rnr[4];
#pragma unroll
    for (int i = 0; i < 4; i++)
        rnr[i] = g_rn_f[b * HW + rowPix[ty * 4 + i]];

    float best[4];  int bestj[4];
#pragma unroll
    for (int i = 0; i < 4; i++) { best[i] = __int_as_float(0xff800000); bestj[i] = 0; }

    for (int jt = 0; jt < NC; jt += 64) {
        __syncthreads();  // As ready (first iter) / previous Bs consumers done
        for (int t = tid; t < 1024; t += 256) {
            int k  = t >> 4;
            int c4 = (t & 15) * 4;
            float4 v = *reinterpret_cast<const float4*>(&Bmat[(size_t)k * NC + jt + c4]);
            *reinterpret_cast<float4*>(&Bs[k * 64 + c4]) = v;
        }
        __syncthreads();

        unsigned long long acc[4][2];
#pragma unroll
        for (int i = 0; i < 4; i++) { acc[i][0] = 0ull; acc[i][1] = 0ull; }

#pragma unroll 8
        for (int k = 0; k < 64; k++) {
            float4 av = *reinterpret_cast<const float4*>(&As[k * 64 + (ty << 2)]);
            ulonglong2 bv = *reinterpret_cast<const ulonglong2*>(&Bs[k * 64 + (tx << 2)]);
            unsigned long long a0 = dup2(av.x), a1 = dup2(av.y),
                               a2 = dup2(av.z), a3 = dup2(av.w);
            ffma2(acc[0][0], a0, bv.x);  ffma2(acc[0][1], a0, bv.y);
            ffma2(acc[1][0], a1, bv.x);  ffma2(acc[1][1], a1, bv.y);
            ffma2(acc[2][0], a2, bv.x);  ffma2(acc[2][1], a2, bv.y);
            ffma2(acc[3][0], a3, bv.x);  ffma2(acc[3][1], a3, bv.y);
        }

        // epilogue: scale + fold into running (max, first-occurrence argmax)
        int   ccol[4];
        float csc[4];
#pragma unroll
        for (int jj = 0; jj < 4; jj++) {
            ccol[jj] = cidx[jt + (tx << 2) + jj];
            csc [jj] = rnc [jt + (tx << 2) + jj];
        }
#pragma unroll
        for (int i = 0; i < 4; i++) {
            float2 lo = *reinterpret_cast<float2*>(&acc[i][0]);
            float2 hi = *reinterpret_cast<float2*>(&acc[i][1]);
            float vv[4] = {lo.x, lo.y, hi.x, hi.y};
#pragma unroll
            for (int jj = 0; jj < 4; jj++) {
                float v = vv[jj] * csc[jj] * rnr[i];
                if (v > best[i]) { best[i] = v; bestj[i] = ccol[jj]; }
            }
        }
    }

    // cross-thread reduction over 16 column-slices per row
    __syncthreads();
    float* rv = Bs;
    int*   rj = reinterpret_cast<int*>(As);
#pragma unroll
    for (int i = 0; i < 4; i++) {
        rv[(ty * 4 + i) * 16 + tx] = best[i];
        rj[(ty * 4 + i) * 16 + tx] = bestj[i];
    }
    __syncthreads();
    if (tid < 64) {
        float bv = __int_as_float(0xff800000);
        int bj = 0x7fffffff;
        for (int t = 0; t < 16; t++) {
            float v  = rv[tid * 16 + t];
            int   j2 = rj[tid * 16 + t];
            if (v > bv || (v == bv && j2 < bj)) { bv = v; bj = j2; }
        }
        int gi = b * MH + rowBlk * 64 + tid;
        g_max[br][gi] = bv;
        g_arg[br][gi] = bj;
    }
}

// ---------------- epilogue chain -------------------------------------------
__global__ void zero_kernel()
{
    int t = blockIdx.x * 256 + threadIdx.x;
    if (t < 2 * BATCH * HW) (&g_colflag[0][0])[t] = 0;
    if (t < BATCH * HW) g_selmap[t] = 0;
}

__global__ void scatter_kernel(const int* __restrict__ p)
{
    int t = blockIdx.x * 256 + threadIdx.x;
    if (t >= BATCH * MH) return;
    int b = t / MH;
    g_colflag[0][b * HW + g_arg[0][t]] = 1;
    g_colflag[1][b * HW + g_arg[1][t]] = 1;
    int pix = p[t];
    if (pix != 0)
        g_selmap[b * HW + pix] = (g_max[0][t] >= g_max[1][t]) ? 1 : 2;
}

__global__ void ssum_kernel(const float* __restrict__ x, const float* __restrict__ flip)
{
    int c  = blockIdx.x;
    int b  = blockIdx.y;
    int br = blockIdx.z;
    const float* Bmat = br ? (flip + (size_t)b * CF * HW)
                           : (x + (size_t)b * CHAN * HW + (size_t)CF * HW);
    const int* cfl = g_colflag[br] + b * HW;
    float s = 0.f;
    for (int j = threadIdx.x; j < HW; j += 256)
        if (cfl[j]) s += Bmat[(size_t)c * HW + j];
    __shared__ float red[256];
    red[threadIdx.x] = s;
    __syncthreads();
    for (int off = 128; off > 0; off >>= 1) {
        if (threadIdx.x < off) red[threadIdx.x] += red[threadIdx.x + off];
        __syncthreads();
    }
    if (threadIdx.x == 0) g_S[b][br][c] = red[0];
}

__global__ void out_kernel(const float* __restrict__ x, float* __restrict__ out)
{
    unsigned int idx = blockIdx.x * 256u + threadIdx.x;
    const unsigned int total = BATCH * 192u * HW;
    if (idx >= total) return;
    unsigned int b   = idx / (192u * HW);
    unsigned int rem = idx - b * 192u * HW;
    unsigned int ch  = rem / HW;
    unsigned int j   = rem - ch * HW;
    float v;
    if (ch < CHAN) {
        v = x[(size_t)b * CHAN * HW + rem];
    } else {
        int s = g_selmap[b * HW + j];
        v = s ? g_S[b][s - 1][ch - CHAN] : 0.f;
    }
    out[idx] = v;
}

// ---------------- launch ----------------------------------------------------
extern "C" void kernel_launch(void* const* d_in, const int* in_sizes, int n_in,
                              void* d_out, int out_size)
{
    const float* x     = (const float*)d_in[0];
    const float* flip  = (const float*)d_in[1];
    const int*   flag  = (const int*)d_in[2];
    const int*   flagf = (const int*)d_in[3];
    const int*   p     = (const int*)d_in[4];
    const int*   q     = (const int*)d_in[5];
    float* out = (float*)d_out;

    norms_kernel   <<<dim3(HW / 256, BATCH), 256>>>(x, flip);
    compact_kernel <<<dim3(BATCH, 2), 1024>>>(flag, flagf);
    bgather_kernel <<<dim3(NC / 256, CF, BATCH * 2), 256>>>(x, flip);
    score_kernel   <<<dim3(MH / 64, BATCH, 2), 256>>>(x, p, q);
    zero_kernel    <<<(2 * BATCH * HW + 255) / 256, 256>>>();
    scatter_kernel <<<(BATCH * MH + 255) / 256, 256>>>(p);
    ssum_kernel    <<<dim3(CF, BATCH, 2), 256>>>(x, flip);
    out_kernel     <<<(BATCH * 192 * HW + 255) / 256, 256>>>(x, out);
}